// round 16
// baseline (speedup 1.0000x reference)
#include <cuda_runtime.h>
#include <cstdint>
#include <math.h>

#define B_    32
#define C_    128
#define O_    256
#define HWD   32
#define L_    1024
#define CKK   1152
#define S_    9
#define SUBK  128
#define BOL   8388608       // B*O*L  (s-stride in y)
#define OLl   262144        // O*L    (b-stride in y)

// ---------------- device scratch ----------------
__device__ __align__(16) int8_t  g_qi[B_*C_*HWD*HWD];
__device__ __align__(16) int8_t  g_qw[O_*CKK];
__device__ __align__(16) int8_t  g_qa[(size_t)B_*L_*CKK];
__device__ __align__(16) short   g_y[(size_t)S_*BOL];
__device__ int                g_S1[S_*O_];       // exact integer sum y_int
__device__ unsigned long long g_S2[S_*O_];       // exact integer sum y_int^2
__device__ float g_A[S_*O_];   // inv_std*gamma/3
__device__ float g_Bc[S_*O_];  // beta - mean*inv_std*gamma

// ---------------- compile-time threefry keys ----------------
constexpr uint32_t crotl(uint32_t x, int r){ return (x << r) | (x >> (32 - r)); }
struct KP { uint32_t a, b; };
constexpr KP host_tf(uint32_t k0, uint32_t k1, uint32_t x0, uint32_t x1){
  uint32_t ks2 = k0 ^ k1 ^ 0x1BD11BDAu;
  x0 += k0; x1 += k1;
  const int RA[4] = {13,15,26,6};
  const int RB[4] = {17,29,16,24};
  const uint32_t ka[5] = {k1, ks2, k0, k1, ks2};
  const uint32_t kb[5] = {ks2, k0, k1, ks2, k0};
  for (int blk = 0; blk < 5; blk++){
    const int* R = (blk & 1) ? RB : RA;
    for (int i = 0; i < 4; i++){ x0 += x1; x1 = crotl(x1, R[i]); x1 ^= x0; }
    x0 += ka[blk]; x1 += kb[blk] + (uint32_t)(blk + 1);
  }
  return KP{x0, x1};
}
// fold_in(key(42), t) = threefry2x32(key=[0,42], data=[0,t])
constexpr KP KEY0 = host_tf(0u, 42u, 0u, 0u);
constexpr KP KEY1 = host_tf(0u, 42u, 0u, 1u);
constexpr KP KEY2 = host_tf(0u, 42u, 0u, 2u);
constexpr KP KEY3 = host_tf(0u, 42u, 0u, 3u);

// ---- R4/R10-proven threefry config ----
#define TF_ROUND(r) { x0 += x1; x1 = __funnelshift_l(x1, x1, (r)); x1 ^= x0; }
#define TF_ROUND_M(r) { x0 += x1; \
  x1 = (x1 * (1u << (r))) + __umulhi(x1, 1u << (r)); x1 ^= x0; }

template<uint32_t K0, uint32_t K1>
__device__ __forceinline__ uint32_t tf_bits(uint32_t ctr){
  constexpr uint32_t KS2 = K0 ^ K1 ^ 0x1BD11BDAu;
  uint32_t x0 = K0;            // ctr_hi = 0
  uint32_t x1 = ctr + K1;
  TF_ROUND(13) TF_ROUND(15) TF_ROUND_M(26) TF_ROUND(6)
  x0 += K1;  x1 += KS2 + 1u;
  TF_ROUND(17) TF_ROUND(29) TF_ROUND(16) TF_ROUND(24)
  x0 += KS2; x1 += K0 + 2u;
  TF_ROUND(13) TF_ROUND(15) TF_ROUND_M(26) TF_ROUND(6)
  x0 += K0;  x1 += K1 + 3u;
  TF_ROUND(17) TF_ROUND(29) TF_ROUND(16) TF_ROUND(24)
  x0 += K1;  x1 += KS2 + 4u;
  TF_ROUND(13) TF_ROUND(15) TF_ROUND_M(26) TF_ROUND(6)
  x0 += KS2; x1 += K0 + 5u;
  return x0 ^ x1;              // partitionable: out = w0 ^ w1
}

// ---------------- k0: zero the stat accumulators (graph-replay safe) ----------------
__global__ void k_zero_stats(){
  int i = blockIdx.x * 256 + threadIdx.x;
  if (i < S_*O_){ g_S1[i] = 0; g_S2[i] = 0ull; }
}

// ---------------- k1: quantize input ----------------
__global__ void k_quant_input(const float* __restrict__ in, int n){
  int i = blockIdx.x * 256 + threadIdx.x;
  if (i < n){
    float v = fminf(fmaxf(in[i], -1.0f), 1.0f);
    g_qi[i] = (int8_t)__float2int_rn(v * 3.0f);
  }
}

// ---------------- k2: weight sign ----------------
__global__ void k_qw(const float* __restrict__ w){
  int o = blockIdx.x, t = threadIdx.x;
  const float* wr = w + (size_t)o * CKK;
  double s = 0.0;
  for (int i = t; i < CKK; i += 128) s += (double)wr[i];
  __shared__ double sh[128];
  sh[t] = s; __syncthreads();
  for (int d = 64; d; d >>= 1){ if (t < d) sh[t] += sh[t + d]; __syncthreads(); }
  float m = (float)(sh[0] / (double)CKK);
  for (int i = t; i < CKK; i += 128){
    float d = wr[i] - m;
    g_qw[(size_t)o * CKK + i] = (int8_t)((d > 0.0f) - (d < 0.0f));
  }
}

// ---------------- k3: im2col — register packing + smem-staged coalesced output ----------------
__global__ void k_im2col(){
  int bid = blockIdx.x;                 // B*32 blocks: (b, out-row y0)
  int b = bid >> 5, y0 = bid & 31;
  int t = threadIdx.x;                  // 256
  __shared__ __align__(16) int8_t so_[HWD * CKK];  // 36 KB staged output tile
  __shared__ int8_t sq[C_ * 3 * HWD];              // 12 KB input slab [c][dy][x]
  for (int i = t; i < C_ * 3 * HWD; i += 256){
    int c = i / 96, rr = (i % 96) >> 5, x = i & 31;
    int yy = y0 + rr - 1;
    sq[i] = (yy >= 0 && yy < HWD) ? g_qi[((size_t)(b * C_ + c) * HWD + yy) * HWD + x] : (int8_t)0;
  }
  __syncthreads();
  // build: c4 fast (bank-conflict-free STS: word stride 9, coprime with 32)
  #pragma unroll
  for (int i = t; i < 32 * 32; i += 256){
    int c4 = i & 31, x0 = i >> 5;
    union { int8_t bt[36]; uint32_t w[9]; } pk;
    #pragma unroll
    for (int cc = 0; cc < 4; cc++){
      int c = c4 * 4 + cc;
      const int8_t* row = sq + 3 * 32 * c;   // [dy][x]
      #pragma unroll
      for (int j = 0; j < 9; j++){
        const int dy = j / 3, dx = j % 3;    // compile-time constants
        int xx = x0 + dx - 1;
        pk.bt[cc * 9 + j] = (xx >= 0 && xx < 32) ? row[dy * 32 + xx] : (int8_t)0;
      }
    }
    uint32_t* d4 = (uint32_t*)(so_ + x0 * CKK + c4 * 36);  // 4B-aligned STS
    #pragma unroll
    for (int k = 0; k < 9; k++) d4[k] = pk.w[k];
  }
  __syncthreads();
  // coalesced int4 copy smem -> gmem (2304 int4, 9 per thread)
  int4* dst = (int4*)(g_qa + (size_t)(b * L_ + y0 * HWD) * CKK);
  const int4* src = (const int4*)so_;
  #pragma unroll
  for (int i = t; i < (HWD * CKK) / 16; i += 256) dst[i] = src[i];
}

// ---------------- k4: int8 GEMM (dp4a) + fused BN-stat accumulation ----------------
__global__ void __launch_bounds__(256) k_gemm(){
  int l0 = blockIdx.x * 128, o0 = blockIdx.y * 64;
  int sb = blockIdx.z, s = sb >> 5, b = sb & 31;
  __shared__ __align__(16) int8_t sA[128][144];
  __shared__ __align__(16) int8_t sW[64][144];
  int t = threadIdx.x;
  const int8_t* gA = g_qa + (size_t)(b * L_ + l0) * CKK + s * SUBK;
  const int8_t* gW = g_qw + (size_t)o0 * CKK + s * SUBK;
  #pragma unroll
  for (int m = t; m < 1024; m += 256){
    int row = m >> 3, c16 = (m & 7) * 16;
    *(int4*)&sA[row][c16] = *(const int4*)(gA + (size_t)row * CKK + c16);
  }
  #pragma unroll
  for (int m = t; m < 512; m += 256){
    int row = m >> 3, c16 = (m & 7) * 16;
    *(int4*)&sW[row][c16] = *(const int4*)(gW + (size_t)row * CKK + c16);
  }
  __syncthreads();
  int tx = t & 15, ty = t >> 4;
  int acc[4][8] = {};
  #pragma unroll
  for (int kc = 0; kc < 8; kc++){
    int4 a4[8], w4[4];
    #pragma unroll
    for (int il = 0; il < 8; il++) a4[il] = *(const int4*)&sA[tx + 16 * il][kc * 16];
    #pragma unroll
    for (int io = 0; io < 4; io++) w4[io] = *(const int4*)&sW[ty + 16 * io][kc * 16];
    #pragma unroll
    for (int io = 0; io < 4; io++)
      #pragma unroll
      for (int il = 0; il < 8; il++){
        acc[io][il] = __dp4a(a4[il].x, w4[io].x, acc[io][il]);
        acc[io][il] = __dp4a(a4[il].y, w4[io].y, acc[io][il]);
        acc[io][il] = __dp4a(a4[il].z, w4[io].z, acc[io][il]);
        acc[io][il] = __dp4a(a4[il].w, w4[io].w, acc[io][il]);
      }
  }
  size_t base = (size_t)s * BOL + (size_t)b * OLl;
  #pragma unroll
  for (int io = 0; io < 4; io++)
    #pragma unroll
    for (int il = 0; il < 8; il++)
      g_y[base + (size_t)(o0 + ty + 16 * io) * 1024 + (l0 + tx + 16 * il)] = (short)acc[io][il];

  // fused BN statistics: exact integer sums per (s, o-row)
  #pragma unroll
  for (int io = 0; io < 4; io++){
    int s1 = 0, s2 = 0;
    #pragma unroll
    for (int il = 0; il < 8; il++){
      int v = acc[io][il];
      s1 += v; s2 += v * v;
    }
    #pragma unroll
    for (int d = 8; d; d >>= 1){
      s1 += __shfl_down_sync(0xffffffffu, s1, d, 16);
      s2 += __shfl_down_sync(0xffffffffu, s2, d, 16);
    }
    if (tx == 0){
      int so = s * 256 + (o0 + ty + 16 * io);
      atomicAdd(&g_S1[so], s1);
      atomicAdd(&g_S2[so], (unsigned long long)(unsigned int)s2);
    }
  }
}

// ---------------- k5: finalize BN coefficients ----------------
__global__ void k_finalize(const float* __restrict__ gamma, const float* __restrict__ beta){
  int so = blockIdx.x * 256 + threadIdx.x;
  if (so >= S_*O_) return;
  int o = so & 255;
  const double N = 32768.0;
  double mean = (double)g_S1[so] / (3.0 * N);
  double e2   = (double)g_S2[so] / (9.0 * N);
  double var  = e2 - mean * mean;
  double inv  = (double)gamma[o] / sqrt(var + 1e-5);
  g_A[so]  = (float)(inv / 3.0);
  g_Bc[so] = (float)((double)beta[o] - mean * inv);
}

// ---------------- k6: sampling with intra-warp compaction (R11-proven) ----------------
// u < p  <=>  (float)(bits>>9) < p*2^23  (exact). p23==2^23 -> cnt=4 always; p23==0 -> 0.
__global__ void __launch_bounds__(256) k_sample(float* __restrict__ out){
  int tid = threadIdx.x;
  int wid = tid >> 5, lane = tid & 31;
  uint32_t j = blockIdx.x * 256 + tid;            // flat (b,o,l)
  uint32_t jw = j - lane;                         // warp-base j
  int o = (j >> 10) & 255;

  __shared__ float          sp23[8][S_][32];      // per-warp thresholds
  __shared__ unsigned short slist[8][S_ * 32];    // packed (s*32+lane) entries
  __shared__ int            scnt[8][32];          // per-source-lane count

  scnt[wid][lane] = 0;

  short yv[S_];
  #pragma unroll
  for (int s = 0; s < S_; s++) yv[s] = __ldg(&g_y[(size_t)s * BOL + j]);

  int nfull = 0, nlist = 0;
  #pragma unroll
  for (int s = 0; s < S_; s++){
    float A  = __ldg(&g_A[s * 256 + o]);
    float Bc = __ldg(&g_Bc[s * 256 + o]);
    float zf = fmaf((float)yv[s], A, Bc);
    zf = fminf(fmaxf(zf, -1.0f), 1.0f);
    float p = fminf(fmaxf((zf + 1.0f) * 0.5f, 0.0f), 1.0f);
    float ps = p * 8388608.0f;                    // exact
    sp23[wid][s][lane] = ps;
    bool full = (ps == 8388608.0f);
    bool zero = (ps == 0.0f);
    nfull += full;
    unsigned m = __ballot_sync(0xffffffffu, !full && !zero);
    if (!full && !zero)
      slist[wid][nlist + __popc(m & ((1u << lane) - 1u))] =
          (unsigned short)(s * 32 + lane);
    nlist += __popc(m);
  }
  __syncwarp();

  for (int e = lane; e < nlist; e += 32){
    int ent = slist[wid][e];
    int es = ent >> 5, el = ent & 31;
    float ps = sp23[wid][es][el];
    uint32_t idx = (uint32_t)es * BOL + jw + (uint32_t)el;
    uint32_t b0 = tf_bits<KEY0.a, KEY0.b>(idx);
    uint32_t b1 = tf_bits<KEY1.a, KEY1.b>(idx);
    uint32_t b2 = tf_bits<KEY2.a, KEY2.b>(idx);
    uint32_t b3 = tf_bits<KEY3.a, KEY3.b>(idx);
    int c = ((float)__umulhi(b0, 8388608u) < ps)
          + ((float)__umulhi(b1, 8388608u) < ps)
          + ((float)__umulhi(b2, 8388608u) < ps)
          + ((float)__umulhi(b3, 8388608u) < ps);
    atomicAdd(&scnt[wid][el], c);
  }
  __syncwarp();

  int total = 4 * nfull + scnt[wid][lane];
  out[j] = (2.0f * (float)total - 36.0f) * (1.0f / 36.0f);
}

extern "C" void kernel_launch(void* const* d_in, const int* in_sizes, int n_in,
                              void* d_out, int out_size) {
  const float* inputs = (const float*)d_in[0];
  const float* weight = (const float*)d_in[1];
  const float* gamma  = (const float*)d_in[2];
  const float* beta   = (const float*)d_in[3];
  float* out = (float*)d_out;

  k_zero_stats<<<(S_*O_ + 255) / 256, 256>>>();
  k_quant_input<<<(B_*C_*HWD*HWD + 255) / 256, 256>>>(inputs, B_*C_*HWD*HWD);
  k_qw<<<O_, 128>>>(weight);
  k_im2col<<<B_ * 32, 256>>>();
  dim3 gg(8, 4, S_ * B_);
  k_gemm<<<gg, 256>>>();
  k_finalize<<<(S_*O_ + 255) / 256, 256>>>(gamma, beta);
  k_sample<<<BOL / 256, 256>>>(out);
}

// round 17
// speedup vs baseline: 1.1083x; 1.1083x over previous
#include <cuda_runtime.h>
#include <cstdint>
#include <math.h>

#define B_    32
#define C_    128
#define O_    256
#define HWD   32
#define L_    1024
#define CKK   1152
#define S_    9
#define SUBK  128
#define BOL   8388608       // B*O*L  (s-stride in y)
#define OLl   262144        // O*L    (b-stride in y)

// ---------------- device scratch ----------------
__device__ __align__(16) int8_t  g_qi[B_*C_*HWD*HWD];
__device__ __align__(16) int8_t  g_qw[O_*CKK];
__device__ __align__(16) int8_t  g_qa[(size_t)B_*L_*CKK];
__device__ __align__(16) short   g_y[(size_t)S_*BOL];
__device__ int                g_S1[S_*O_];       // exact integer sum y_int
__device__ unsigned long long g_S2[S_*O_];       // exact integer sum y_int^2
__device__ float g_A[S_*O_];   // inv_std*gamma/3
__device__ float g_Bc[S_*O_];  // beta - mean*inv_std*gamma

// ---------------- compile-time threefry keys ----------------
constexpr uint32_t crotl(uint32_t x, int r){ return (x << r) | (x >> (32 - r)); }
struct KP { uint32_t a, b; };
constexpr KP host_tf(uint32_t k0, uint32_t k1, uint32_t x0, uint32_t x1){
  uint32_t ks2 = k0 ^ k1 ^ 0x1BD11BDAu;
  x0 += k0; x1 += k1;
  const int RA[4] = {13,15,26,6};
  const int RB[4] = {17,29,16,24};
  const uint32_t ka[5] = {k1, ks2, k0, k1, ks2};
  const uint32_t kb[5] = {ks2, k0, k1, ks2, k0};
  for (int blk = 0; blk < 5; blk++){
    const int* R = (blk & 1) ? RB : RA;
    for (int i = 0; i < 4; i++){ x0 += x1; x1 = crotl(x1, R[i]); x1 ^= x0; }
    x0 += ka[blk]; x1 += kb[blk] + (uint32_t)(blk + 1);
  }
  return KP{x0, x1};
}
// fold_in(key(42), t) = threefry2x32(key=[0,42], data=[0,t])
constexpr KP KEY0 = host_tf(0u, 42u, 0u, 0u);
constexpr KP KEY1 = host_tf(0u, 42u, 0u, 1u);
constexpr KP KEY2 = host_tf(0u, 42u, 0u, 2u);
constexpr KP KEY3 = host_tf(0u, 42u, 0u, 3u);

// ---- R4/R10-proven threefry config ----
#define TF_ROUND(r) { x0 += x1; x1 = __funnelshift_l(x1, x1, (r)); x1 ^= x0; }
#define TF_ROUND_M(r) { x0 += x1; \
  x1 = (x1 * (1u << (r))) + __umulhi(x1, 1u << (r)); x1 ^= x0; }

template<uint32_t K0, uint32_t K1>
__device__ __forceinline__ uint32_t tf_bits(uint32_t ctr){
  constexpr uint32_t KS2 = K0 ^ K1 ^ 0x1BD11BDAu;
  uint32_t x0 = K0;            // ctr_hi = 0
  uint32_t x1 = ctr + K1;
  TF_ROUND(13) TF_ROUND(15) TF_ROUND_M(26) TF_ROUND(6)
  x0 += K1;  x1 += KS2 + 1u;
  TF_ROUND(17) TF_ROUND(29) TF_ROUND(16) TF_ROUND(24)
  x0 += KS2; x1 += K0 + 2u;
  TF_ROUND(13) TF_ROUND(15) TF_ROUND_M(26) TF_ROUND(6)
  x0 += K0;  x1 += K1 + 3u;
  TF_ROUND(17) TF_ROUND(29) TF_ROUND(16) TF_ROUND(24)
  x0 += K1;  x1 += KS2 + 4u;
  TF_ROUND(13) TF_ROUND(15) TF_ROUND_M(26) TF_ROUND(6)
  x0 += KS2; x1 += K0 + 5u;
  return x0 ^ x1;              // partitionable: out = w0 ^ w1
}

// ---------------- k0: zero the stat accumulators (graph-replay safe) ----------------
__global__ void k_zero_stats(){
  int i = blockIdx.x * 256 + threadIdx.x;
  if (i < S_*O_){ g_S1[i] = 0; g_S2[i] = 0ull; }
}

// ---------------- k1: quantize input (float4 -> 4 bytes) ----------------
__global__ void k_quant_input(const float* __restrict__ in, int n4){
  int i = blockIdx.x * 256 + threadIdx.x;
  if (i < n4){
    float4 v = ((const float4*)in)[i];
    uchar4 r;
    r.x = (uint8_t)(int8_t)__float2int_rn(fminf(fmaxf(v.x, -1.0f), 1.0f) * 3.0f);
    r.y = (uint8_t)(int8_t)__float2int_rn(fminf(fmaxf(v.y, -1.0f), 1.0f) * 3.0f);
    r.z = (uint8_t)(int8_t)__float2int_rn(fminf(fmaxf(v.z, -1.0f), 1.0f) * 3.0f);
    r.w = (uint8_t)(int8_t)__float2int_rn(fminf(fmaxf(v.w, -1.0f), 1.0f) * 3.0f);
    ((uchar4*)g_qi)[i] = r;
  }
}

// ---------------- k2: weight sign ----------------
__global__ void k_qw(const float* __restrict__ w){
  int o = blockIdx.x, t = threadIdx.x;
  const float* wr = w + (size_t)o * CKK;
  double s = 0.0;
  for (int i = t; i < CKK; i += 128) s += (double)wr[i];
  __shared__ double sh[128];
  sh[t] = s; __syncthreads();
  for (int d = 64; d; d >>= 1){ if (t < d) sh[t] += sh[t + d]; __syncthreads(); }
  float m = (float)(sh[0] / (double)CKK);
  for (int i = t; i < CKK; i += 128){
    float d = wr[i] - m;
    g_qw[(size_t)o * CKK + i] = (int8_t)((d > 0.0f) - (d < 0.0f));
  }
}

// ---------------- k3: im2col — R11 pattern, division-free, 4 bytes/thread/iter ----------------
__global__ void k_im2col(){
  int bid = blockIdx.x;                 // B*32 blocks: (b, out-row y0)
  int b = bid >> 5, y0 = bid & 31;
  int t = threadIdx.x;                  // 256
  __shared__ int8_t sq[C_ * 3 * HWD];   // [c][dy][x]
  for (int i = t; i < C_ * 3 * HWD; i += 256){
    int c = i / 96, rr = (i % 96) >> 5, x = i & 31;
    int yy = y0 + rr - 1;
    sq[i] = (yy >= 0 && yy < HWD) ? g_qi[((size_t)(b * C_ + c) * HWD + yy) * HWD + x] : (int8_t)0;
  }
  __syncthreads();
  int8_t* dst = g_qa + (size_t)(b * L_ + y0 * HWD) * CKK;
  // word widx handles bytes base=4*widx..+3 of the [x0][ckk] tile; ckk = c*9 + j.
  // carried indices: base += 1024 each iter (1024 = 113*9 + 7).
  int base = t * 4;
  int x0 = base / CKK;
  int ck = base - x0 * CKK;
  int c  = ck / 9;
  int j  = ck - c * 9;
  #pragma unroll 4
  for (int q = 0; q < 36; q++){
    uint32_t w = 0;
    int cc = c, jj = j;
    #pragma unroll
    for (int k = 0; k < 4; k++){
      int dy = (jj * 11) >> 5;          // jj/3 for jj in [0,8]
      int dx = jj - dy * 3;
      int xx = x0 + dx - 1;
      int8_t v = (xx >= 0 && xx < 32) ? sq[(cc * 3 + dy) * 32 + xx] : (int8_t)0;
      w |= ((uint32_t)(uint8_t)v) << (8 * k);
      jj++; if (jj == 9){ jj = 0; cc++; }
    }
    *(uint32_t*)(dst + base) = w;       // 4B-aligned, lanes consecutive -> coalesced
    base += 1024;
    ck += 1024; j += 7; c += 113;
    if (j >= 9){ j -= 9; c += 1; }
    if (ck >= CKK){ ck -= CKK; c -= 128; x0 += 1; }
  }
}

// ---------------- k4: int8 GEMM (dp4a) + fused BN-stat accumulation ----------------
__global__ void __launch_bounds__(256) k_gemm(){
  int l0 = blockIdx.x * 128, o0 = blockIdx.y * 64;
  int sb = blockIdx.z, s = sb >> 5, b = sb & 31;
  __shared__ __align__(16) int8_t sA[128][144];
  __shared__ __align__(16) int8_t sW[64][144];
  int t = threadIdx.x;
  const int8_t* gA = g_qa + (size_t)(b * L_ + l0) * CKK + s * SUBK;
  const int8_t* gW = g_qw + (size_t)o0 * CKK + s * SUBK;
  #pragma unroll
  for (int m = t; m < 1024; m += 256){
    int row = m >> 3, c16 = (m & 7) * 16;
    *(int4*)&sA[row][c16] = *(const int4*)(gA + (size_t)row * CKK + c16);
  }
  #pragma unroll
  for (int m = t; m < 512; m += 256){
    int row = m >> 3, c16 = (m & 7) * 16;
    *(int4*)&sW[row][c16] = *(const int4*)(gW + (size_t)row * CKK + c16);
  }
  __syncthreads();
  int tx = t & 15, ty = t >> 4;
  int acc[4][8] = {};
  #pragma unroll
  for (int kc = 0; kc < 8; kc++){
    int4 a4[8], w4[4];
    #pragma unroll
    for (int il = 0; il < 8; il++) a4[il] = *(const int4*)&sA[tx + 16 * il][kc * 16];
    #pragma unroll
    for (int io = 0; io < 4; io++) w4[io] = *(const int4*)&sW[ty + 16 * io][kc * 16];
    #pragma unroll
    for (int io = 0; io < 4; io++)
      #pragma unroll
      for (int il = 0; il < 8; il++){
        acc[io][il] = __dp4a(a4[il].x, w4[io].x, acc[io][il]);
        acc[io][il] = __dp4a(a4[il].y, w4[io].y, acc[io][il]);
        acc[io][il] = __dp4a(a4[il].z, w4[io].z, acc[io][il]);
        acc[io][il] = __dp4a(a4[il].w, w4[io].w, acc[io][il]);
      }
  }
  size_t base = (size_t)s * BOL + (size_t)b * OLl;
  #pragma unroll
  for (int io = 0; io < 4; io++)
    #pragma unroll
    for (int il = 0; il < 8; il++)
      g_y[base + (size_t)(o0 + ty + 16 * io) * 1024 + (l0 + tx + 16 * il)] = (short)acc[io][il];

  // fused BN statistics: exact integer sums per (s, o-row)
  #pragma unroll
  for (int io = 0; io < 4; io++){
    int s1 = 0, s2 = 0;
    #pragma unroll
    for (int il = 0; il < 8; il++){
      int v = acc[io][il];
      s1 += v; s2 += v * v;
    }
    #pragma unroll
    for (int d = 8; d; d >>= 1){
      s1 += __shfl_down_sync(0xffffffffu, s1, d, 16);
      s2 += __shfl_down_sync(0xffffffffu, s2, d, 16);
    }
    if (tx == 0){
      int so = s * 256 + (o0 + ty + 16 * io);
      atomicAdd(&g_S1[so], s1);
      atomicAdd(&g_S2[so], (unsigned long long)(unsigned int)s2);
    }
  }
}

// ---------------- k5: finalize BN coefficients ----------------
__global__ void k_finalize(const float* __restrict__ gamma, const float* __restrict__ beta){
  int so = blockIdx.x * 256 + threadIdx.x;
  if (so >= S_*O_) return;
  int o = so & 255;
  const double N = 32768.0;
  double mean = (double)g_S1[so] / (3.0 * N);
  double e2   = (double)g_S2[so] / (9.0 * N);
  double var  = e2 - mean * mean;
  double inv  = (double)gamma[o] / sqrt(var + 1e-5);
  g_A[so]  = (float)(inv / 3.0);
  g_Bc[so] = (float)((double)beta[o] - mean * inv);
}

// ---------------- k6: sampling with intra-warp compaction (R11-proven) ----------------
// u < p  <=>  (float)(bits>>9) < p*2^23  (exact). p23==2^23 -> cnt=4 always; p23==0 -> 0.
__global__ void __launch_bounds__(256) k_sample(float* __restrict__ out){
  int tid = threadIdx.x;
  int wid = tid >> 5, lane = tid & 31;
  uint32_t j = blockIdx.x * 256 + tid;            // flat (b,o,l)
  uint32_t jw = j - lane;                         // warp-base j
  int o = (j >> 10) & 255;

  __shared__ float          sp23[8][S_][32];      // per-warp thresholds
  __shared__ unsigned short slist[8][S_ * 32];    // packed (s*32+lane) entries
  __shared__ int            scnt[8][32];          // per-source-lane count

  scnt[wid][lane] = 0;

  short yv[S_];
  #pragma unroll
  for (int s = 0; s < S_; s++) yv[s] = __ldg(&g_y[(size_t)s * BOL + j]);

  int nfull = 0, nlist = 0;
  #pragma unroll
  for (int s = 0; s < S_; s++){
    float A  = __ldg(&g_A[s * 256 + o]);
    float Bc = __ldg(&g_Bc[s * 256 + o]);
    float zf = fmaf((float)yv[s], A, Bc);
    zf = fminf(fmaxf(zf, -1.0f), 1.0f);
    float p = fminf(fmaxf((zf + 1.0f) * 0.5f, 0.0f), 1.0f);
    float ps = p * 8388608.0f;                    // exact
    sp23[wid][s][lane] = ps;
    bool full = (ps == 8388608.0f);
    bool zero = (ps == 0.0f);
    nfull += full;
    unsigned m = __ballot_sync(0xffffffffu, !full && !zero);
    if (!full && !zero)
      slist[wid][nlist + __popc(m & ((1u << lane) - 1u))] =
          (unsigned short)(s * 32 + lane);
    nlist += __popc(m);
  }
  __syncwarp();

  for (int e = lane; e < nlist; e += 32){
    int ent = slist[wid][e];
    int es = ent >> 5, el = ent & 31;
    float ps = sp23[wid][es][el];
    uint32_t idx = (uint32_t)es * BOL + jw + (uint32_t)el;
    uint32_t b0 = tf_bits<KEY0.a, KEY0.b>(idx);
    uint32_t b1 = tf_bits<KEY1.a, KEY1.b>(idx);
    uint32_t b2 = tf_bits<KEY2.a, KEY2.b>(idx);
    uint32_t b3 = tf_bits<KEY3.a, KEY3.b>(idx);
    int c = ((float)__umulhi(b0, 8388608u) < ps)
          + ((float)__umulhi(b1, 8388608u) < ps)
          + ((float)__umulhi(b2, 8388608u) < ps)
          + ((float)__umulhi(b3, 8388608u) < ps);
    atomicAdd(&scnt[wid][el], c);
  }
  __syncwarp();

  int total = 4 * nfull + scnt[wid][lane];
  out[j] = (2.0f * (float)total - 36.0f) * (1.0f / 36.0f);
}

extern "C" void kernel_launch(void* const* d_in, const int* in_sizes, int n_in,
                              void* d_out, int out_size) {
  const float* inputs = (const float*)d_in[0];
  const float* weight = (const float*)d_in[1];
  const float* gamma  = (const float*)d_in[2];
  const float* beta   = (const float*)d_in[3];
  float* out = (float*)d_out;

  k_zero_stats<<<(S_*O_ + 255) / 256, 256>>>();
  k_quant_input<<<(B_*C_*HWD*HWD / 4 + 255) / 256, 256>>>(inputs, B_*C_*HWD*HWD / 4);
  k_qw<<<O_, 128>>>(weight);
  k_im2col<<<B_ * 32, 256>>>();
  dim3 gg(8, 4, S_ * B_);
  k_gemm<<<gg, 256>>>();
  k_finalize<<<(S_*O_ + 255) / 256, 256>>>(gamma, beta);
  k_sample<<<BOL / 256, 256>>>(out);
}